// round 1
// baseline (speedup 1.0000x reference)
#include <cuda_runtime.h>

// ---------------------------------------------------------------------------
// CrossAtt fp32 baseline for GB300.
// Shapes (fixed): B=8, H=W=64 -> N=4096, DIM=640, HEADS=8, SEG=128, CH=64.
// ---------------------------------------------------------------------------

#define RSQ_BN 0.9999950000374997f      // 1/sqrt(1+1e-5)
#define SCALE_V 0.11180339887498949f    // (640/8)^-0.5
#define LN_EPS 1e-5f

__device__ __forceinline__ float hsw(float x) {
    return x * fminf(fmaxf(x + 3.f, 0.f), 6.f) * (1.f / 6.f);
}

// ---------------- scratch (single bss array, no allocations) ---------------
// layout (floats):
//  kv     :         0  .. 41,943,040   (8,4096,1280)
//  Qh     : 41,943,040 (+16,777,216)   (8,8,4096,64)
//  Kh     : 58,720,256 (+16,777,216)
//  Vh     : 75,497,472 (+16,777,216)
//  crpe   : 92,274,688 (+16,777,216)
//  tmp    :109,051,904 (+ 4,194,304)   (32768,128) dwconv scratch
//  locraw :113,246,208 (+ 4,194,304)
//  obuf   :117,440,512 (+20,971,520)   (8,4096,640)
//  mx     :138,412,032 (+4096)
//  sm     :138,416,128 (+4096)
//  kTv    :138,420,224 (+262,144)
//  total  :138,682,368 floats = 554.7 MB
static __device__ __align__(256) float g_scratch[138682368ULL];

// ---------------------------------------------------------------------------
// Tiled SGEMM: C[M,N] = A[M,K] * W[N,K]^T  (W row-major (N,K))
// BM=BN=128, BK=8, 256 threads, 8x8 per thread.
// MODE 0: C[m*ldc+n] = acc
// MODE 1: C[m*ldc+n] = acc + p2[n]                      (bias)
// MODE 2: v = hswish(acc * (p1[n]*RSQ_BN) + p2[n]);     (BN eval + hardswish)
//         scatter to head buffer C[((b*8+h)*4096+nn)*64+cc],
//         b=m>>12, nn=m&4095, h=headBase+(n>>6), cc=n&63
// Requires M%128==0, N%128==0, K%8==0 (true for all uses here).
// ---------------------------------------------------------------------------
template <int MODE>
__global__ void __launch_bounds__(256) sgemm_k(
    const float* __restrict__ A, int lda,
    const float* __restrict__ W,
    float* __restrict__ C, int ldc,
    int M, int N, int K,
    const float* __restrict__ p1, const float* __restrict__ p2, int headBase)
{
    __shared__ float As[8][128];
    __shared__ float Bs[8][128];

    const int tid  = threadIdx.x;
    const int rowL = tid >> 1;          // 0..127
    const int colL = (tid & 1) << 2;    // 0 or 4

    const float* Ab = A + ((long)blockIdx.y * 128 + rowL) * (long)lda + colL;
    const float* Wb = W + ((long)blockIdx.x * 128 + rowL) * (long)K + colL;

    const int tr = tid >> 4;   // 0..15 (row group)
    const int tc = tid & 15;   // 0..15 (col group)

    float acc[8][8];
#pragma unroll
    for (int i = 0; i < 8; i++)
#pragma unroll
        for (int j = 0; j < 8; j++) acc[i][j] = 0.f;

    for (int k0 = 0; k0 < K; k0 += 8) {
        float4 a4 = *reinterpret_cast<const float4*>(Ab + k0);
        float4 b4 = *reinterpret_cast<const float4*>(Wb + k0);
        As[colL + 0][rowL] = a4.x; As[colL + 1][rowL] = a4.y;
        As[colL + 2][rowL] = a4.z; As[colL + 3][rowL] = a4.w;
        Bs[colL + 0][rowL] = b4.x; Bs[colL + 1][rowL] = b4.y;
        Bs[colL + 2][rowL] = b4.z; Bs[colL + 3][rowL] = b4.w;
        __syncthreads();
#pragma unroll
        for (int k = 0; k < 8; k++) {
            float4 a0 = *reinterpret_cast<const float4*>(&As[k][tr * 8]);
            float4 a1 = *reinterpret_cast<const float4*>(&As[k][tr * 8 + 4]);
            float4 b0 = *reinterpret_cast<const float4*>(&Bs[k][tc * 8]);
            float4 b1 = *reinterpret_cast<const float4*>(&Bs[k][tc * 8 + 4]);
            float ra[8] = {a0.x, a0.y, a0.z, a0.w, a1.x, a1.y, a1.z, a1.w};
            float rb[8] = {b0.x, b0.y, b0.z, b0.w, b1.x, b1.y, b1.z, b1.w};
#pragma unroll
            for (int i = 0; i < 8; i++)
#pragma unroll
                for (int j = 0; j < 8; j++)
                    acc[i][j] = fmaf(ra[i], rb[j], acc[i][j]);
        }
        __syncthreads();
    }

    const int m0 = blockIdx.y * 128 + tr * 8;
    const int n0 = blockIdx.x * 128 + tc * 8;
#pragma unroll
    for (int i = 0; i < 8; i++) {
        const int m = m0 + i;
#pragma unroll
        for (int j = 0; j < 8; j++) {
            const int n = n0 + j;
            float v = acc[i][j];
            if (MODE == 0) {
                C[(long)m * ldc + n] = v;
            } else if (MODE == 1) {
                C[(long)m * ldc + n] = v + p2[n];
            } else {
                v = v * (p1[n] * RSQ_BN) + p2[n];
                v = hsw(v);
                const int b = m >> 12, nn = m & 4095;
                const int h = headBase + (n >> 6), cc = n & 63;
                C[((((long)b * 8 + h) * 4096) + nn) * 64 + cc] = v;
            }
        }
    }
}

// ---------------------------------------------------------------------------
// seg0 branch: hardswish(BN(x)) -> head layout (heads 0,1)
// grid (2048, 8), block (128, 2)
// ---------------------------------------------------------------------------
__global__ void seg0_k(const float* __restrict__ in, int inRow,
                       float* __restrict__ hb,
                       const float* __restrict__ g, const float* __restrict__ bb)
{
    const int c = threadIdx.x;                       // 0..127
    const int n = blockIdx.x * blockDim.y + threadIdx.y;
    const int b = blockIdx.y;
    float v = in[((long)b * 4096 + n) * (long)inRow + c];
    v = v * (g[c] * RSQ_BN) + bb[c];
    v = hsw(v);
    const int h = c >> 6, cc = c & 63;
    hb[(((long)b * 8 + h) * 4096 + n) * 64 + cc] = v;
}

// ---------------------------------------------------------------------------
// Generic depthwise conv on a 64x64 image, channel-last rows.
// batch index = blockIdx.y = outer*nh + inner; weight channel = inner*C + c.
// in pixel (n,c) at in + outer*inOuter + inner*inInner + n*inRow + c
// out pixel at out + outer*outOuter + inner*outInner + n*C + c
// dynamic smem: C*KS*KS floats.
// ---------------------------------------------------------------------------
template <int KS>
__global__ void dwconv_k(const float* __restrict__ in, long inOuter, long inInner, int inRow,
                         float* __restrict__ out, long outOuter, long outInner,
                         const float* __restrict__ w, int C, int nh)
{
    extern __shared__ float ws[];
    const int batch = blockIdx.y;
    const int outer = batch / nh, inner = batch % nh;
    const float* ip = in + outer * inOuter + inner * inInner;
    float* op = out + outer * outOuter + inner * outInner;
    const float* wp = w + (long)inner * C * KS * KS;

    const int nthr = blockDim.x * blockDim.y;
    const int tid = threadIdx.y * blockDim.x + threadIdx.x;
    for (int i = tid; i < C * KS * KS; i += nthr) ws[i] = wp[i];
    __syncthreads();

    const int c = threadIdx.x;
    const int pix = blockIdx.x * blockDim.y + threadIdx.y;
    const int y = pix >> 6, x = pix & 63;
    const int P = KS / 2;
    float acc = 0.f;
#pragma unroll
    for (int dy = 0; dy < KS; dy++) {
        const int yy = y + dy - P;
        if (yy < 0 || yy > 63) continue;
#pragma unroll
        for (int dx = 0; dx < KS; dx++) {
            const int xx = x + dx - P;
            if (xx < 0 || xx > 63) continue;
            acc = fmaf(ws[c * KS * KS + dy * KS + dx],
                       ip[(long)(yy * 64 + xx) * inRow + c], acc);
        }
    }
    op[(long)pix * C + c] = acc;
}

// ---------------------------------------------------------------------------
// Softmax stats over tokens (axis N) per (b,h,c): max and sum(exp(x-max)).
// Also zeroes the kTv accumulator slice for this (b,h).
// grid 64 (= b*h), block 512 (c = tid&63, 8 n-slices).
// ---------------------------------------------------------------------------
__global__ void softstats_k(const float* __restrict__ Kh,
                            float* __restrict__ mx, float* __restrict__ sm,
                            float* __restrict__ ktv)
{
    const int bh = blockIdx.x;
    const int c  = threadIdx.x & 63;
    const int sl = threadIdx.x >> 6;    // 0..7
    const float* kp = Kh + (long)bh * 4096 * 64;

    // zero kTv slice
    float* kz = ktv + (long)bh * 4096;
    for (int i = threadIdx.x; i < 4096; i += 512) kz[i] = 0.f;

    float m = -1e30f;
    for (int j = 0; j < 512; j++) {
        const int n = sl * 512 + j;
        m = fmaxf(m, kp[(long)n * 64 + c]);
    }
    __shared__ float red[512];
    __shared__ float red2[512];
    red[threadIdx.x] = m;
    __syncthreads();
    if (sl == 0) {
        for (int s = 1; s < 8; s++) m = fmaxf(m, red[s * 64 + c]);
        red[c] = m;
    }
    __syncthreads();
    m = red[c];

    float s = 0.f;
    for (int j = 0; j < 512; j++) {
        const int n = sl * 512 + j;
        s += __expf(kp[(long)n * 64 + c] - m);
    }
    red2[threadIdx.x] = s;
    __syncthreads();
    if (sl == 0) {
        for (int ss = 1; ss < 8; ss++) s += red2[ss * 64 + c];
        mx[bh * 64 + c] = m;
        sm[bh * 64 + c] = s;
    }
}

// ---------------------------------------------------------------------------
// kTv[c1,c2] += sum_n softmax(k)[n,c1] * v[n,c2], split over 8 n-chunks.
// grid (8, 64), block 256: 4x4 accumulator tile per thread; atomicAdd reduce.
// ---------------------------------------------------------------------------
__global__ void ktv_k(const float* __restrict__ Kh, const float* __restrict__ Vh,
                      const float* __restrict__ mx, const float* __restrict__ sm,
                      float* __restrict__ ktv)
{
    const int bh = blockIdx.y;
    const int chunk = blockIdx.x;
    const int tid = threadIdx.x;
    __shared__ float sk[4][64];
    __shared__ float sv[4][64];

    const float* kp = Kh + (long)bh * 4096 * 64;
    const float* vp = Vh + (long)bh * 4096 * 64;
    const int lc = tid & 63, lr = tid >> 6;
    const float lm = mx[bh * 64 + lc];
    const float lrs = 1.f / sm[bh * 64 + lc];

    const int i0 = (tid & 15) * 4;   // c1 base
    const int j0 = (tid >> 4) * 4;   // c2 base
    float acc[4][4] = {};

    const int nend = chunk * 512 + 512;
    for (int n0 = chunk * 512; n0 < nend; n0 += 4) {
        sk[lr][lc] = __expf(kp[(long)(n0 + lr) * 64 + lc] - lm) * lrs;
        sv[lr][lc] = vp[(long)(n0 + lr) * 64 + lc];
        __syncthreads();
#pragma unroll
        for (int r = 0; r < 4; r++) {
            float a[4], bv[4];
#pragma unroll
            for (int i = 0; i < 4; i++) a[i] = sk[r][i0 + i];
#pragma unroll
            for (int j = 0; j < 4; j++) bv[j] = sv[r][j0 + j];
#pragma unroll
            for (int i = 0; i < 4; i++)
#pragma unroll
                for (int j = 0; j < 4; j++) acc[i][j] = fmaf(a[i], bv[j], acc[i][j]);
        }
        __syncthreads();
    }
    float* kp2 = ktv + (long)bh * 4096;
#pragma unroll
    for (int i = 0; i < 4; i++)
#pragma unroll
        for (int j = 0; j < 4; j++)
            atomicAdd(&kp2[(i0 + i) * 64 + (j0 + j)], acc[i][j]);
}

// ---------------------------------------------------------------------------
// eff = q @ kTv; o = SCALE*eff + q * crpe -> obuf[b][n][h*64+c2]
// grid (64 n-chunks, 64 bh), block 256; 64n x 64c2 tile per block.
// ---------------------------------------------------------------------------
__global__ void eff_k(const float* __restrict__ Qh, const float* __restrict__ ktv,
                      const float* __restrict__ crpe, float* __restrict__ obuf)
{
    const int bh = blockIdx.y;
    const int b = bh >> 3, h = bh & 7;
    const int n0 = blockIdx.x * 64;
    const int tid = threadIdx.x;

    __shared__ float skt[64][64];
    __shared__ float sq[64][65];

    const float* ktp = ktv + (long)bh * 4096;
    const float* qp  = Qh + ((long)bh * 4096 + n0) * 64;
    for (int i = tid; i < 4096; i += 256) {
        skt[i >> 6][i & 63] = ktp[i];
        sq[i >> 6][i & 63]  = qp[i];
    }
    __syncthreads();

    const int i0 = (tid & 15) * 4;   // n offset in tile
    const int j0 = (tid >> 4) * 4;   // c2 offset
    float acc[4][4] = {};
#pragma unroll
    for (int c1 = 0; c1 < 64; c1++) {
        float a[4], bv[4];
#pragma unroll
        for (int i = 0; i < 4; i++) a[i] = sq[i0 + i][c1];
#pragma unroll
        for (int j = 0; j < 4; j++) bv[j] = skt[c1][j0 + j];
#pragma unroll
        for (int i = 0; i < 4; i++)
#pragma unroll
            for (int j = 0; j < 4; j++) acc[i][j] = fmaf(a[i], bv[j], acc[i][j]);
    }

    const float* crp = crpe + ((long)bh * 4096 + n0) * 64;
#pragma unroll
    for (int i = 0; i < 4; i++) {
        const int n = n0 + i0 + i;
#pragma unroll
        for (int j = 0; j < 4; j++) {
            const int c2 = j0 + j;
            const float q = sq[i0 + i][c2];
            const float cr = q * crp[(long)(i0 + i) * 64 + c2];
            obuf[((long)b * 4096 + n) * 640 + h * 64 + c2] = SCALE_V * acc[i][j] + cr;
        }
    }
}

// ---------------------------------------------------------------------------
// LayerNorm(128) + hardswish, write (or add) into obuf channels [512,640).
// one warp per row; block 256 = 8 rows; grid 4096 (32768 rows).
// ---------------------------------------------------------------------------
__global__ void ln_k(const float* __restrict__ in,
                     const float* __restrict__ g, const float* __restrict__ bb,
                     float* __restrict__ obuf, int addMode)
{
    const int row  = blockIdx.x * 8 + (threadIdx.x >> 5);
    const int lane = threadIdx.x & 31;
    const float* ip = in + (long)row * 128;
    float4 v = reinterpret_cast<const float4*>(ip)[lane];
    float s  = v.x + v.y + v.z + v.w;
    float sq = v.x * v.x + v.y * v.y + v.z * v.z + v.w * v.w;
#pragma unroll
    for (int o = 16; o > 0; o >>= 1) {
        s  += __shfl_xor_sync(0xffffffffu, s, o);
        sq += __shfl_xor_sync(0xffffffffu, sq, o);
    }
    const float m = s * (1.f / 128.f);
    const float var = sq * (1.f / 128.f) - m * m;
    const float r = rsqrtf(var + LN_EPS);
    const int c0 = lane * 4;
    float vals[4] = {v.x, v.y, v.z, v.w};
    float* op = obuf + (long)row * 640 + 512 + c0;
    float out[4];
#pragma unroll
    for (int i = 0; i < 4; i++) {
        float vv = (vals[i] - m) * r * g[c0 + i] + bb[c0 + i];
        vv = hsw(vv);
        out[i] = addMode ? (op[i] + vv) : vv;
    }
    *reinterpret_cast<float4*>(op) = make_float4(out[0], out[1], out[2], out[3]);
}

// ---------------------------------------------------------------------------
// One aggregator stream: seg0 + 3 conv branches (+ optional local branch).
// ---------------------------------------------------------------------------
static void run_stream(const float* base, int rowStride,
                       const float* dw3, const float* dw5, const float* dw7,
                       const float* pw, const float* bng, const float* bnb,
                       float* headbuf, float* tmp, float* locraw, float* obuf,
                       bool doLoc, const float* lng, const float* lnb, int locAdd)
{
    const long inOuter = 4096L * rowStride;
    const long outO = 4096L * 128;

    seg0_k<<<dim3(2048, 8), dim3(128, 2)>>>(base, rowStride, headbuf, bng, bnb);

    // branch 1: seg1, 3x3 (dw3[1]) -> pw[1] -> heads 2,3
    dwconv_k<3><<<dim3(2048, 8), dim3(128, 2), 128 * 9 * 4>>>(
        base + 128, inOuter, 0, rowStride, tmp, outO, 0, dw3 + 128 * 9, 128, 1);
    sgemm_k<2><<<dim3(1, 256), 256>>>(tmp, 128, pw + 16384, headbuf, 0,
                                      32768, 128, 128, bng + 128, bnb + 128, 2);
    // branch 2: seg2, 5x5 -> pw[2] -> heads 4,5
    dwconv_k<5><<<dim3(2048, 8), dim3(128, 2), 128 * 25 * 4>>>(
        base + 256, inOuter, 0, rowStride, tmp, outO, 0, dw5, 128, 1);
    sgemm_k<2><<<dim3(1, 256), 256>>>(tmp, 128, pw + 2 * 16384, headbuf, 0,
                                      32768, 128, 128, bng + 256, bnb + 256, 4);
    // branch 3: seg3, 7x7 -> pw[3] -> heads 6,7
    dwconv_k<7><<<dim3(2048, 8), dim3(128, 2), 128 * 49 * 4>>>(
        base + 384, inOuter, 0, rowStride, tmp, outO, 0, dw7, 128, 1);
    sgemm_k<2><<<dim3(1, 256), 256>>>(tmp, 128, pw + 3 * 16384, headbuf, 0,
                                      32768, 128, 128, bng + 384, bnb + 384, 6);

    if (doLoc) {
        // local: seg4, 3x3 (dw3[0]) -> pw[0] -> LN -> hswish -> obuf[512:640]
        dwconv_k<3><<<dim3(2048, 8), dim3(128, 2), 128 * 9 * 4>>>(
            base + 512, inOuter, 0, rowStride, tmp, outO, 0, dw3, 128, 1);
        sgemm_k<0><<<dim3(1, 256), 256>>>(tmp, 128, pw, locraw, 128,
                                          32768, 128, 128, nullptr, nullptr, 0);
        ln_k<<<4096, 256>>>(locraw, lng, lnb, obuf, locAdd);
    }
}

// ---------------------------------------------------------------------------
extern "C" void kernel_launch(void* const* d_in, const int* in_sizes, int n_in,
                              void* d_out, int out_size)
{
    (void)in_sizes; (void)n_in; (void)out_size;
    const float* x        = (const float*)d_in[0];
    const float* y        = (const float*)d_in[1];
    const float* kv_w     = (const float*)d_in[2];
    const float* proj_w   = (const float*)d_in[3];
    const float* proj_b   = (const float*)d_in[4];
    const float* crpe_w3  = (const float*)d_in[5];
    const float* crpe_w5  = (const float*)d_in[6];
    const float* crpe_w7  = (const float*)d_in[7];
    const float* aq_dw3   = (const float*)d_in[8];
    const float* aq_dw5   = (const float*)d_in[9];
    const float* aq_dw7   = (const float*)d_in[10];
    const float* aq_pw    = (const float*)d_in[11];
    const float* aq_ln_g  = (const float*)d_in[12];
    const float* aq_ln_b  = (const float*)d_in[13];
    const float* aq_bn_g  = (const float*)d_in[14];
    const float* aq_bn_b  = (const float*)d_in[15];
    const float* akv_dw3  = (const float*)d_in[16];
    const float* akv_dw5  = (const float*)d_in[17];
    const float* akv_dw7  = (const float*)d_in[18];
    const float* akv_pw   = (const float*)d_in[19];
    const float* akv_ln_g = (const float*)d_in[20];
    const float* akv_ln_b = (const float*)d_in[21];
    const float* akv_bn_g = (const float*)d_in[22];
    const float* akv_bn_b = (const float*)d_in[23];

    float* sc = nullptr;
    cudaGetSymbolAddress((void**)&sc, g_scratch);
    float* kv     = sc;
    float* Qh     = sc + 41943040ULL;
    float* Kh     = sc + 58720256ULL;
    float* Vh     = sc + 75497472ULL;
    float* crpe   = sc + 92274688ULL;
    float* tmp    = sc + 109051904ULL;
    float* locraw = sc + 113246208ULL;
    float* obuf   = sc + 117440512ULL;
    float* mx     = sc + 138412032ULL;
    float* smv    = sc + 138416128ULL;
    float* ktv    = sc + 138420224ULL;

    // 1) kv = x @ kv_w^T   (32768 x 1280, K=640); channels [0:640)=k, [640:1280)=v
    sgemm_k<0><<<dim3(10, 256), 256>>>(x, 640, kv_w, kv, 1280,
                                       32768, 1280, 640, nullptr, nullptr, 0);

    // 2) aggregators: q (store loc), k (no loc), v (add loc)
    run_stream(y, 640, aq_dw3, aq_dw5, aq_dw7, aq_pw, aq_bn_g, aq_bn_b,
               Qh, tmp, locraw, obuf, true, aq_ln_g, aq_ln_b, 0);
    run_stream(kv, 1280, akv_dw3, akv_dw5, akv_dw7, akv_pw, akv_bn_g, akv_bn_b,
               Kh, tmp, locraw, obuf, false, nullptr, nullptr, 0);
    run_stream(kv + 640, 1280, akv_dw3, akv_dw5, akv_dw7, akv_pw, akv_bn_g, akv_bn_b,
               Vh, tmp, locraw, obuf, true, akv_ln_g, akv_ln_b, 1);

    // 3) attention: softmax stats over tokens, kTv, crpe convs, eff fuse
    softstats_k<<<64, 512>>>(Kh, mx, smv, ktv);
    ktv_k<<<dim3(8, 64), 256>>>(Kh, Vh, mx, smv, ktv);

    const long hs = 4096L * 64;           // per-head image size
    dwconv_k<3><<<dim3(1024, 16), dim3(64, 4), 64 * 9 * 4>>>(
        Vh, 8 * hs, hs, 64, crpe, 8 * hs, hs, crpe_w3, 64, 2);
    dwconv_k<5><<<dim3(1024, 24), dim3(64, 4), 64 * 25 * 4>>>(
        Vh + 2 * hs, 8 * hs, hs, 64, crpe + 2 * hs, 8 * hs, hs, crpe_w5, 64, 3);
    dwconv_k<7><<<dim3(1024, 24), dim3(64, 4), 64 * 49 * 4>>>(
        Vh + 5 * hs, 8 * hs, hs, 64, crpe + 5 * hs, 8 * hs, hs, crpe_w7, 64, 3);

    eff_k<<<dim3(64, 64), 256>>>(Qh, ktv, crpe, obuf);

    // 4) projection: out = obuf @ proj_w^T + proj_b
    sgemm_k<1><<<dim3(5, 256), 256>>>(obuf, 640, proj_w, (float*)d_out, 640,
                                      32768, 640, 640, nullptr, proj_b, 0);
}